// round 1
// baseline (speedup 1.0000x reference)
#include <cuda_runtime.h>
#include <cstdint>

// PatchEmbeddings: out[b, 1+n, h] = (patchify(x)[b,n,:] @ W)[h] + bias[h] + pos[b,1+n,h]
//                  out[b, 0,   h] = cls[b,0,h] + pos[b,0,h]
// Shapes: x (32,512,512,3) f32, W (768,256), bias (256), cls (32,1,256), pos (32,1025,256)
// GEMM: M=32768, K=768, N=256 using mma.sync.m16n8k8 TF32.

#define BM 128
#define BN 128
#define BK 16
#define ASTR 20    // BK + 4  -> conflict-free A-fragment LDS
#define BSTR 136   // BN + 8  -> conflict-free B-fragment LDS
#define KITERS 48  // 768 / BK

__device__ __forceinline__ uint32_t f2tf32(float f) {
    uint32_t r;
    asm("cvt.rna.tf32.f32 %0, %1;" : "=r"(r) : "f"(f));
    return r;
}

__device__ __forceinline__ void mma_tf32(float* c, const uint32_t* a, const uint32_t* b) {
    asm volatile(
        "mma.sync.aligned.m16n8k8.row.col.f32.tf32.tf32.f32 "
        "{%0,%1,%2,%3}, {%4,%5,%6,%7}, {%8,%9}, {%0,%1,%2,%3};"
        : "+f"(c[0]), "+f"(c[1]), "+f"(c[2]), "+f"(c[3])
        : "r"(a[0]), "r"(a[1]), "r"(a[2]), "r"(a[3]), "r"(b[0]), "r"(b[1]));
}

__global__ __launch_bounds__(256)
void patch_gemm_kernel(const float* __restrict__ x,
                       const float* __restrict__ Wmat,
                       const float* __restrict__ bias,
                       const float* __restrict__ pos,
                       float* __restrict__ out)
{
    __shared__ float As[2][BM][ASTR];
    __shared__ float Bs[2][BK][BSTR];

    const int tid    = threadIdx.x;
    const int lane   = tid & 31;
    const int warp   = tid >> 5;
    const int warp_m = warp & 1;   // 0..1 -> 64 rows each
    const int warp_n = warp >> 1;  // 0..3 -> 32 cols each
    const int grp    = lane >> 2;  // 0..7
    const int tg     = lane & 3;   // 0..3

    const int bn = blockIdx.x;     // 0..1   (N tile)
    const int bm = blockIdx.y;     // 0..255 (M tile)

    // ---- A (patchified x) loading geometry: thread loads (m = p*16 + tid>>4, k = tid&15) ----
    const int a_k = tid & 15;
    const int a_m = tid >> 4;      // 0..15
    int abase[8];
    #pragma unroll
    for (int p = 0; p < 8; p++) {
        int gm = bm * BM + p * 16 + a_m;       // global patch token
        int bb = gm >> 10;                     // batch
        int pp = gm & 1023;                    // patch within batch (32x32 grid)
        // base float index of patch (row 0, col 0, ch 0)
        abase[p] = ((bb * 512 + (pp >> 5) * 16) * 512 + (pp & 31) * 16) * 3;
    }

    // ---- B (W) loading geometry: thread loads float4 at (k = p*8 + tid>>5, n = (tid&31)*4) ----
    const int b_r = tid >> 5;           // 0..7
    const int b_c = (tid & 31) * 4;     // 0..124
    const float* Wbase = Wmat + bn * BN + b_c;

    float acc[4][4][4];
    #pragma unroll
    for (int i = 0; i < 4; i++)
        #pragma unroll
        for (int j = 0; j < 4; j++)
            #pragma unroll
            for (int k = 0; k < 4; k++) acc[i][j][k] = 0.f;

    float  ra[8];
    float4 rb[2];

    // ---- prologue: load + store k-tile 0 ----
    {
        const int d    = a_k;                    // k0 = 0
        const int pr   = d / 48;
        const int rem  = d - pr * 48;
        const int aoff = pr * 1536 + rem;        // row stride = 512*3 floats
        #pragma unroll
        for (int p = 0; p < 8; p++) ra[p] = x[abase[p] + aoff];
        #pragma unroll
        for (int p = 0; p < 2; p++)
            rb[p] = *(const float4*)(Wbase + (b_r + p * 8) * 256);

        #pragma unroll
        for (int p = 0; p < 8; p++)
            As[0][p * 16 + a_m][a_k] = __uint_as_float(f2tf32(ra[p]));
        #pragma unroll
        for (int p = 0; p < 2; p++) {
            float4 cv;
            cv.x = __uint_as_float(f2tf32(rb[p].x));
            cv.y = __uint_as_float(f2tf32(rb[p].y));
            cv.z = __uint_as_float(f2tf32(rb[p].z));
            cv.w = __uint_as_float(f2tf32(rb[p].w));
            *(float4*)&Bs[0][b_r + p * 8][b_c] = cv;
        }
    }
    __syncthreads();

    int buf = 0;
    for (int it = 0; it < KITERS; it++) {
        // prefetch next k-tile into registers
        if (it + 1 < KITERS) {
            const int d    = (it + 1) * BK + a_k;
            const int pr   = d / 48;
            const int rem  = d - pr * 48;
            const int aoff = pr * 1536 + rem;
            #pragma unroll
            for (int p = 0; p < 8; p++) ra[p] = x[abase[p] + aoff];
            #pragma unroll
            for (int p = 0; p < 2; p++)
                rb[p] = *(const float4*)(Wbase + ((it + 1) * BK + b_r + p * 8) * 256);
        }

        // compute on current buffer: 2 k-steps of 8
        #pragma unroll
        for (int ks = 0; ks < 2; ks++) {
            const int k0 = ks * 8;
            uint32_t af[4][4], bf[4][2];
            #pragma unroll
            for (int mi = 0; mi < 4; mi++) {
                const int m = warp_m * 64 + mi * 16;
                af[mi][0] = __float_as_uint(As[buf][m + grp    ][k0 + tg    ]);
                af[mi][1] = __float_as_uint(As[buf][m + grp + 8][k0 + tg    ]);
                af[mi][2] = __float_as_uint(As[buf][m + grp    ][k0 + tg + 4]);
                af[mi][3] = __float_as_uint(As[buf][m + grp + 8][k0 + tg + 4]);
            }
            #pragma unroll
            for (int ni = 0; ni < 4; ni++) {
                const int n = warp_n * 32 + ni * 8;
                bf[ni][0] = __float_as_uint(Bs[buf][k0 + tg    ][n + grp]);
                bf[ni][1] = __float_as_uint(Bs[buf][k0 + tg + 4][n + grp]);
            }
            #pragma unroll
            for (int mi = 0; mi < 4; mi++)
                #pragma unroll
                for (int ni = 0; ni < 4; ni++)
                    mma_tf32(acc[mi][ni], af[mi], bf[ni]);
        }

        // store next tile to the other buffer
        if (it + 1 < KITERS) {
            const int nb = buf ^ 1;
            #pragma unroll
            for (int p = 0; p < 8; p++)
                As[nb][p * 16 + a_m][a_k] = __uint_as_float(f2tf32(ra[p]));
            #pragma unroll
            for (int p = 0; p < 2; p++) {
                float4 cv;
                cv.x = __uint_as_float(f2tf32(rb[p].x));
                cv.y = __uint_as_float(f2tf32(rb[p].y));
                cv.z = __uint_as_float(f2tf32(rb[p].z));
                cv.w = __uint_as_float(f2tf32(rb[p].w));
                *(float4*)&Bs[nb][b_r + p * 8][b_c] = cv;
            }
            __syncthreads();
            buf = nb;
        }
    }

    // ---- epilogue: + bias + pos_embedding, write out (rows shifted by +1 for cls) ----
    const int gn0 = bn * BN + warp_n * 32;
    #pragma unroll
    for (int mi = 0; mi < 4; mi++) {
        const int gm0 = bm * BM + warp_m * 64 + mi * 16 + grp;
        #pragma unroll
        for (int half = 0; half < 2; half++) {
            const int r     = gm0 + half * 8;
            const int bb    = r >> 10;
            const int tok   = r & 1023;
            const int obase = (bb * 1025 + 1 + tok) * 256;
            #pragma unroll
            for (int ni = 0; ni < 4; ni++) {
                const int n = gn0 + ni * 8 + 2 * tg;
                float2 pv = *(const float2*)(pos + obase + n);
                float2 bv = *(const float2*)(bias + n);
                float2 o;
                o.x = acc[mi][ni][half * 2 + 0] + bv.x + pv.x;
                o.y = acc[mi][ni][half * 2 + 1] + bv.y + pv.y;
                *(float2*)(out + obase + n) = o;
            }
        }
    }
}

// Row 0 of each batch: cls_token + pos_embedding
__global__ void cls_kernel(const float* __restrict__ cls,
                           const float* __restrict__ pos,
                           float* __restrict__ out)
{
    int i = blockIdx.x * blockDim.x + threadIdx.x;
    if (i < 32 * 256) {
        int b = i >> 8;
        int h = i & 255;
        int o = b * 1025 * 256 + h;
        out[o] = cls[i] + pos[o];
    }
}

extern "C" void kernel_launch(void* const* d_in, const int* in_sizes, int n_in,
                              void* d_out, int out_size)
{
    const float* x    = (const float*)d_in[0];
    const float* W    = (const float*)d_in[1];
    const float* bias = (const float*)d_in[2];
    const float* cls  = (const float*)d_in[3];
    const float* pos  = (const float*)d_in[4];
    float* out = (float*)d_out;

    dim3 grid(2, 256);   // N tiles x M tiles
    patch_gemm_kernel<<<grid, 256>>>(x, W, bias, pos, out);
    cls_kernel<<<32, 256>>>(cls, pos, out);
}

// round 3
// speedup vs baseline: 1.2036x; 1.2036x over previous
#include <cuda_runtime.h>
#include <cuda_fp16.h>
#include <cstdint>

// PatchEmbeddings: out[b,1+n,h] = (patchify(x)[b,n,:] @ W)[h] + bias[h] + pos[b,1+n,h]
//                  out[b,0,h]   = cls[b,0,h] + pos[b,0,h]
// GEMM M=32768, K=768, N=256 via mma.sync.m16n8k16 FP16 (fp32 accum).
// fp16 keeps tf32's 10-bit mantissa but doubles K per tensor instruction.

#define BM 128
#define BN 128
#define BK 16
#define KITERS 48
#define ROWH 36   // half elements per smem row (16 data + 20 pad) -> 72B stride

__device__ __forceinline__ void mma_f16(float* c, const uint32_t* a, const uint32_t* b) {
    asm volatile(
        "mma.sync.aligned.m16n8k16.row.col.f32.f16.f16.f32 "
        "{%0,%1,%2,%3}, {%4,%5,%6,%7}, {%8,%9}, {%0,%1,%2,%3};"
        : "+f"(c[0]), "+f"(c[1]), "+f"(c[2]), "+f"(c[3])
        : "r"(a[0]), "r"(a[1]), "r"(a[2]), "r"(a[3]), "r"(b[0]), "r"(b[1]));
}

__global__ __launch_bounds__(256, 2)
void patch_gemm_f16(const float* __restrict__ x,
                    const float* __restrict__ Wmat,
                    const float* __restrict__ bias,
                    const float* __restrict__ cls,
                    const float* __restrict__ pos,
                    float* __restrict__ out)
{
    __shared__ __half As[2][BM][ROWH];
    __shared__ __half Bs[2][BN][ROWH];

    const int tid    = threadIdx.x;
    const int lane   = tid & 31;
    const int warp   = tid >> 5;
    const int warp_m = warp & 1;    // 64 rows each
    const int warp_n = warp >> 1;   // 32 cols each
    const int grp    = lane >> 2;
    const int tg     = lane & 3;

    const int bn = blockIdx.x;      // 0..1
    const int bm = blockIdx.y;      // 0..255

    // ---- fold cls row: CTAs bm<32 handle batch=bm, half bn ----
    if (bm < 32 && tid < 128) {
        int h = bn * 128 + tid;
        int o = bm * 1025 * 256 + h;
        out[o] = cls[bm * 256 + h] + pos[o];
    }

    // ---- A loader geometry: thread = (m = tid>>3 (+32p), k-pair g = tid&7) ----
    const int am = tid >> 3;
    const int g  = tid & 7;
    const int k2 = g * 2;
    int abase[4];
    #pragma unroll
    for (int p = 0; p < 4; p++) {
        int r  = bm * BM + am + 32 * p;
        int bb = r >> 10, pp = r & 1023;
        abase[p] = ((bb * 512 + (pp >> 5) * 16) * 512 + (pp & 31) * 16) * 3;
    }

    // ---- B loader geometry: thread = (n = tid&127, k-half kh = tid>>7) ----
    const int b_n  = tid & 127;
    const int b_kh = (tid >> 7) * 8;
    const float* Wp = Wmat + bn * BN + b_n + b_kh * 256;

    float acc[4][4][4];
    #pragma unroll
    for (int i = 0; i < 4; i++)
        #pragma unroll
        for (int j = 0; j < 4; j++)
            #pragma unroll
            for (int k = 0; k < 4; k++) acc[i][j][k] = 0.f;

    float2 ra[4];
    float  rb[8];

    // ---- prologue: k-tile 0 -> buf 0 ----
    {
        const int aoff = k2;  // it=0: pr=0, rem=0
        #pragma unroll
        for (int p = 0; p < 4; p++) ra[p] = *(const float2*)(x + abase[p] + aoff);
        #pragma unroll
        for (int j = 0; j < 8; j++) rb[j] = Wp[j * 256];

        #pragma unroll
        for (int p = 0; p < 4; p++)
            *(__half2*)&As[0][am + 32 * p][k2] = __floats2half2_rn(ra[p].x, ra[p].y);
        #pragma unroll
        for (int j = 0; j < 4; j++)
            *(__half2*)&Bs[0][b_n][b_kh + 2 * j] = __floats2half2_rn(rb[2 * j], rb[2 * j + 1]);
    }
    __syncthreads();

    int buf = 0;
    for (int it = 0; it < KITERS; it++) {
        // prefetch next k-tile (BK=16 divides patch-row width 48: no row crossing)
        if (it + 1 < KITERS) {
            const int itn  = it + 1;
            const int pr   = itn / 3;
            const int aoff = pr * 1536 + (itn - pr * 3) * 16 + k2;
            #pragma unroll
            for (int p = 0; p < 4; p++) ra[p] = *(const float2*)(x + abase[p] + aoff);
            const float* wp = Wp + itn * 16 * 256;
            #pragma unroll
            for (int j = 0; j < 8; j++) rb[j] = wp[j * 256];
        }

        // ---- compute: one m16n8k16 step over BK=16 ----
        {
            uint32_t af[4][4], bf[4][2];
            #pragma unroll
            for (int mi = 0; mi < 4; mi++) {
                const int m = warp_m * 64 + mi * 16;
                af[mi][0] = *(const uint32_t*)&As[buf][m + grp    ][2 * tg    ];
                af[mi][1] = *(const uint32_t*)&As[buf][m + grp + 8][2 * tg    ];
                af[mi][2] = *(const uint32_t*)&As[buf][m + grp    ][2 * tg + 8];
                af[mi][3] = *(const uint32_t*)&As[buf][m + grp + 8][2 * tg + 8];
            }
            #pragma unroll
            for (int ni = 0; ni < 4; ni++) {
                const int n = warp_n * 32 + ni * 8 + grp;
                bf[ni][0] = *(const uint32_t*)&Bs[buf][n][2 * tg    ];
                bf[ni][1] = *(const uint32_t*)&Bs[buf][n][2 * tg + 8];
            }
            #pragma unroll
            for (int mi = 0; mi < 4; mi++)
                #pragma unroll
                for (int ni = 0; ni < 4; ni++)
                    mma_f16(acc[mi][ni], af[mi], bf[ni]);
        }

        // ---- store prefetched tile into other buffer ----
        if (it + 1 < KITERS) {
            const int nb = buf ^ 1;
            #pragma unroll
            for (int p = 0; p < 4; p++)
                *(__half2*)&As[nb][am + 32 * p][k2] = __floats2half2_rn(ra[p].x, ra[p].y);
            #pragma unroll
            for (int j = 0; j < 4; j++)
                *(__half2*)&Bs[nb][b_n][b_kh + 2 * j] = __floats2half2_rn(rb[2 * j], rb[2 * j + 1]);
            __syncthreads();
            buf = nb;
        }
    }

    // ---- epilogue: + bias + pos, rows shifted +1 for cls ----
    const int gn0 = bn * BN + warp_n * 32;
    #pragma unroll
    for (int mi = 0; mi < 4; mi++) {
        const int gm0 = bm * BM + warp_m * 64 + mi * 16 + grp;
        #pragma unroll
        for (int half = 0; half < 2; half++) {
            const int r     = gm0 + half * 8;
            const int bb    = r >> 10;
            const int tok   = r & 1023;
            const int obase = (bb * 1025 + 1 + tok) * 256;
            #pragma unroll
            for (int ni = 0; ni < 4; ni++) {
                const int n = gn0 + ni * 8 + 2 * tg;
                float2 pv = *(const float2*)(pos + obase + n);
                float2 bv = *(const float2*)(bias + n);
                float2 o;
                o.x = acc[mi][ni][half * 2 + 0] + bv.x + pv.x;
                o.y = acc[mi][ni][half * 2 + 1] + bv.y + pv.y;
                *(float2*)(out + obase + n) = o;
            }
        }
    }
}

extern "C" void kernel_launch(void* const* d_in, const int* in_sizes, int n_in,
                              void* d_out, int out_size)
{
    const float* x    = (const float*)d_in[0];
    const float* W    = (const float*)d_in[1];
    const float* bias = (const float*)d_in[2];
    const float* cls  = (const float*)d_in[3];
    const float* pos  = (const float*)d_in[4];
    float* out = (float*)d_out;

    dim3 grid(2, 256);
    patch_gemm_f16<<<grid, 256>>>(x, W, bias, cls, pos, out);
}

// round 4
// speedup vs baseline: 1.6336x; 1.3572x over previous
#include <cuda_runtime.h>
#include <cuda_fp16.h>
#include <cstdint>

// PatchEmbeddings: out[b,1+n,h] = (patchify(x)[b,n,:] @ W)[h] + bias[h] + pos[b,1+n,h]
//                  out[b,0,h]   = cls[b,0,h] + pos[b,0,h]
// GEMM M=32768, K=768, N=256; mma.sync.m16n8k16 f16 (fp32 accum), ldmatrix fragments.

#define KITERS 48

__device__ __forceinline__ void mma_f16(float* c, const uint32_t* a, const uint32_t* b) {
    asm volatile(
        "mma.sync.aligned.m16n8k16.row.col.f32.f16.f16.f32 "
        "{%0,%1,%2,%3}, {%4,%5,%6,%7}, {%8,%9}, {%0,%1,%2,%3};"
        : "+f"(c[0]), "+f"(c[1]), "+f"(c[2]), "+f"(c[3])
        : "r"(a[0]), "r"(a[1]), "r"(a[2]), "r"(a[3]), "r"(b[0]), "r"(b[1]));
}

__device__ __forceinline__ void ldsm4(uint32_t& r0, uint32_t& r1, uint32_t& r2,
                                      uint32_t& r3, uint32_t addr) {
    asm volatile("ldmatrix.sync.aligned.m8n8.x4.shared.b16 {%0,%1,%2,%3}, [%4];"
                 : "=r"(r0), "=r"(r1), "=r"(r2), "=r"(r3) : "r"(addr));
}

__device__ __forceinline__ uint32_t pack2(float a, float b) {
    __half2 h = __floats2half2_rn(a, b);
    return *reinterpret_cast<uint32_t*>(&h);
}

// swizzled byte offset of 16B chunk (row, k8) in a 128x16-half tile (32B rows)
__device__ __forceinline__ uint32_t tile_off(int row, int k8) {
    return (uint32_t)(row * 32 + ((k8 ^ ((row >> 2) & 1)) << 4));
}

__global__ __launch_bounds__(256, 2)
void patch_gemm_f16(const float* __restrict__ x,
                    const float* __restrict__ Wmat,
                    const float* __restrict__ bias,
                    const float* __restrict__ cls,
                    const float* __restrict__ pos,
                    float* __restrict__ out)
{
    __shared__ __align__(128) uint8_t As[2][4096];
    __shared__ __align__(128) uint8_t Bs[2][4096];

    const int tid    = threadIdx.x;
    const int lane   = tid & 31;
    const int warp   = tid >> 5;
    const int warp_m = warp & 1;    // 64 m-rows
    const int warp_n = warp >> 1;   // 32 n-cols

    const int bn = blockIdx.x;      // 0..1
    const int bm = blockIdx.y;      // 0..255

    const uint32_t As_b = (uint32_t)__cvta_generic_to_shared(&As[0][0]);
    const uint32_t Bs_b = (uint32_t)__cvta_generic_to_shared(&Bs[0][0]);

    // ---- fold cls row ----
    if (bm < 32 && tid < 128) {
        int h = bn * 128 + tid;
        int o = bm * 1025 * 256 + h;
        out[o] = cls[bm * 256 + h] + pos[o];
    }

    // ---- A producer: thread -> (m = tid>>1, k8 = tid&1), one 16B chunk/iter ----
    const int alm = tid >> 1;
    const int ak8 = tid & 1;
    int abase;
    {
        int r = bm * 128 + alm;
        int bb = r >> 10, pp = r & 1023;
        abase = ((bb * 512 + (pp >> 5) * 16) * 512 + (pp & 31) * 16) * 3 + ak8 * 8;
    }
    const uint32_t a_sts = tile_off(alm, ak8);

    // ---- B producer: thread -> (n = tid&127, k8 = tid>>7) ----
    const int bln = tid & 127;
    const int bk8 = tid >> 7;
    const float* Wcol = Wmat + bn * 128 + bln + bk8 * 8 * 256;
    const uint32_t b_sts = tile_off(bln, bk8);

    // ---- per-lane ldmatrix addresses ----
    const int ar = warp_m * 64 + (lane & 15);
    const uint32_t a_frag = As_b + tile_off(ar, lane >> 4);
    const int br = warp_n * 32 + ((lane >> 4) << 3) + (lane & 7);
    const uint32_t b_frag = Bs_b + tile_off(br, (lane >> 3) & 1);

    float acc[4][4][4];
    #pragma unroll
    for (int i = 0; i < 4; i++)
        #pragma unroll
        for (int j = 0; j < 4; j++)
            #pragma unroll
            for (int k = 0; k < 4; k++) acc[i][j][k] = 0.f;

    // ---- prologue: k-tile 0 -> buf 0 ----
    {
        float4 va0 = *(const float4*)(x + abase);
        float4 va1 = *(const float4*)(x + abase + 4);
        uint4 ua;
        ua.x = pack2(va0.x, va0.y); ua.y = pack2(va0.z, va0.w);
        ua.z = pack2(va1.x, va1.y); ua.w = pack2(va1.z, va1.w);
        *(uint4*)(&As[0][a_sts]) = ua;

        float wb[8];
        #pragma unroll
        for (int j = 0; j < 8; j++) wb[j] = Wcol[j * 256];
        uint4 ub;
        ub.x = pack2(wb[0], wb[1]); ub.y = pack2(wb[2], wb[3]);
        ub.z = pack2(wb[4], wb[5]); ub.w = pack2(wb[6], wb[7]);
        *(uint4*)(&Bs[0][b_sts]) = ub;
    }
    __syncthreads();

    int buf = 0;
    #pragma unroll 6
    for (int it = 0; it < KITERS; it++) {
        // ---- prefetch k-tile it+1 into registers ----
        float4 va0, va1; float wb[8];
        if (it + 1 < KITERS) {
            const int itn = it + 1;
            const int pr  = itn / 3;                       // patch pixel-row
            const float* xa = x + abase + pr * 1536 + (itn - pr * 3) * 16;
            va0 = *(const float4*)xa;
            va1 = *(const float4*)(xa + 4);
            const float* wp = Wcol + itn * (16 * 256);
            #pragma unroll
            for (int j = 0; j < 8; j++) wb[j] = wp[j * 256];
        }

        // ---- fragments via ldmatrix + 16 HMMA ----
        {
            const uint32_t ab = a_frag + buf * 4096;
            const uint32_t bb = b_frag + buf * 4096;
            uint32_t af[4][4], bf[4][2];
            #pragma unroll
            for (int mi = 0; mi < 4; mi++)
                ldsm4(af[mi][0], af[mi][1], af[mi][2], af[mi][3], ab + mi * 512);
            ldsm4(bf[0][0], bf[0][1], bf[1][0], bf[1][1], bb);
            ldsm4(bf[2][0], bf[2][1], bf[3][0], bf[3][1], bb + 512);
            #pragma unroll
            for (int mi = 0; mi < 4; mi++)
                #pragma unroll
                for (int ni = 0; ni < 4; ni++)
                    mma_f16(acc[mi][ni], af[mi], bf[ni]);
        }

        // ---- commit prefetched tile to other buffer ----
        if (it + 1 < KITERS) {
            const int nb = buf ^ 1;
            uint4 ua;
            ua.x = pack2(va0.x, va0.y); ua.y = pack2(va0.z, va0.w);
            ua.z = pack2(va1.x, va1.y); ua.w = pack2(va1.z, va1.w);
            *(uint4*)(&As[nb][a_sts]) = ua;
            uint4 ub;
            ub.x = pack2(wb[0], wb[1]); ub.y = pack2(wb[2], wb[3]);
            ub.z = pack2(wb[4], wb[5]); ub.w = pack2(wb[6], wb[7]);
            *(uint4*)(&Bs[nb][b_sts]) = ub;
            __syncthreads();
            buf = nb;
        }
    }

    // ---- epilogue: + bias + pos, rows shifted +1 for cls ----
    const int grp = lane >> 2;
    const int tg  = lane & 3;
    const int gn0 = bn * 128 + warp_n * 32;

    float2 bv[4];
    #pragma unroll
    for (int ni = 0; ni < 4; ni++)
        bv[ni] = *(const float2*)(bias + gn0 + ni * 8 + 2 * tg);

    #pragma unroll
    for (int mi = 0; mi < 4; mi++) {
        const int gm0 = bm * 128 + warp_m * 64 + mi * 16 + grp;
        #pragma unroll
        for (int half = 0; half < 2; half++) {
            const int r     = gm0 + half * 8;
            const int bb    = r >> 10;
            const int tok   = r & 1023;
            const int obase = (bb * 1025 + 1 + tok) * 256;
            #pragma unroll
            for (int ni = 0; ni < 4; ni++) {
                const int n = gn0 + ni * 8 + 2 * tg;
                float2 pv = *(const float2*)(pos + obase + n);
                float2 o;
                o.x = acc[mi][ni][half * 2 + 0] + bv[ni].x + pv.x;
                o.y = acc[mi][ni][half * 2 + 1] + bv[ni].y + pv.y;
                *(float2*)(out + obase + n) = o;
            }
        }
    }
}

extern "C" void kernel_launch(void* const* d_in, const int* in_sizes, int n_in,
                              void* d_out, int out_size)
{
    const float* x    = (const float*)d_in[0];
    const float* W    = (const float*)d_in[1];
    const float* bias = (const float*)d_in[2];
    const float* cls  = (const float*)d_in[3];
    const float* pos  = (const float*)d_in[4];
    float* out = (float*)d_out;

    dim3 grid(2, 256);
    patch_gemm_f16<<<grid, 256>>>(x, W, bias, cls, pos, out);
}

// round 5
// speedup vs baseline: 1.9797x; 1.2119x over previous
#include <cuda_runtime.h>
#include <cuda_fp16.h>
#include <cstdint>

// PatchEmbeddings: out[b,1+n,h] = (patchify(x)[b,n,:] @ W)[h] + bias[h] + pos[b,1+n,h]
//                  out[b,0,h]   = cls[b,0,h] + pos[b,0,h]
// GEMM M=32768, K=768, N=256; m16n8k16 f16 MMA, BK=48 (one pixel row / k-tile).
// W pre-converted to fp16 and pre-tiled by a tiny prekernel; B tiles stream in
// via cp.async. A tiles are contiguous 6KB runs thanks to BK=48.

#define ITERS 16

__device__ __align__(16) uint8_t WT[2u * 16u * 768u * 16u];  // 384 KB tiled fp16 W

// ---------------- helpers ----------------
__device__ __forceinline__ void mma_f16(float* c, const uint32_t* a, const uint32_t* b) {
    asm volatile(
        "mma.sync.aligned.m16n8k16.row.col.f32.f16.f16.f32 "
        "{%0,%1,%2,%3}, {%4,%5,%6,%7}, {%8,%9}, {%0,%1,%2,%3};"
        : "+f"(c[0]), "+f"(c[1]), "+f"(c[2]), "+f"(c[3])
        : "r"(a[0]), "r"(a[1]), "r"(a[2]), "r"(a[3]), "r"(b[0]), "r"(b[1]));
}

__device__ __forceinline__ void ldsm4(uint32_t& r0, uint32_t& r1, uint32_t& r2,
                                      uint32_t& r3, uint32_t addr) {
    asm volatile("ldmatrix.sync.aligned.m8n8.x4.shared.b16 {%0,%1,%2,%3}, [%4];"
                 : "=r"(r0), "=r"(r1), "=r"(r2), "=r"(r3) : "r"(addr));
}

__device__ __forceinline__ uint32_t pack2(float a, float b) {
    __half2 h = __floats2half2_rn(a, b);
    return *reinterpret_cast<uint32_t*>(&h);
}

#define CP_ASYNC16(dst, src) \
    asm volatile("cp.async.cg.shared.global [%0], [%1], 16;" :: "r"(dst), "l"(src) : "memory")
#define CP_COMMIT() asm volatile("cp.async.commit_group;" ::: "memory")
#define CP_WAIT0()  asm volatile("cp.async.wait_group 0;" ::: "memory")

// ---------------- prekernel: W -> fp16, transposed + tile-ordered ----------------
// WT block b = bn*16 + it holds 768 16B-chunks; chunk l: n = l/6, c = l%6,
// halves = W[it*48 + c*8 .. +8][bn*128 + n].
__global__ void prep_w(const float* __restrict__ W) {
    const int b  = blockIdx.x;          // 0..31
    const int bn = b >> 4, it = b & 15;
    const int t  = threadIdx.x;         // 256
    #pragma unroll
    for (int j = 0; j < 3; j++) {
        const int l = t + 256 * j;      // 0..767
        const int n = l / 6, c = l % 6;
        const float* src = W + (it * 48 + c * 8) * 256 + bn * 128 + n;
        uint4 u;
        u.x = pack2(src[0 * 256], src[1 * 256]);
        u.y = pack2(src[2 * 256], src[3 * 256]);
        u.z = pack2(src[4 * 256], src[5 * 256]);
        u.w = pack2(src[6 * 256], src[7 * 256]);
        *(uint4*)(WT + ((size_t)b * 768 + l) * 16) = u;
    }
}

// ---------------- main kernel ----------------
__global__ __launch_bounds__(256, 2)
void patch_gemm(const float* __restrict__ x,
                const float* __restrict__ bias,
                const float* __restrict__ cls,
                const float* __restrict__ pos,
                float* __restrict__ out)
{
    extern __shared__ __align__(128) uint8_t smem[];
    // layout: A[buf] @ buf*16384 (128 rows x 128B), B[buf] @ 32768 + buf*16384

    const int tid    = threadIdx.x;
    const int lane   = tid & 31;
    const int warp   = tid >> 5;
    const int warp_m = warp & 1;
    const int warp_n = warp >> 1;
    const int bn = blockIdx.x;      // 0..1
    const int bm = blockIdx.y;      // 0..255

    const uint32_t sbase = (uint32_t)__cvta_generic_to_shared(smem);

    // ---- fold cls row ----
    if (bm < 32 && tid < 128) {
        int h = bn * 128 + tid;
        int o = bm * 1025 * 256 + h;
        out[o] = cls[bm * 256 + h] + pos[o];
    }

    // ---- A loader geometry: 1536 float4/iter, thread gets 6 ----
    const int bb = bm >> 3;
    int a_src[6];        // float index, add it*1536 per iter
    uint32_t a_dst[6];   // smem byte offset within A tile
    #pragma unroll
    for (int j = 0; j < 6; j++) {
        const int l   = tid + 256 * j;        // 0..1535 float4 units
        const int seg = l / 384;              // 4 segments = 4 patch-grid rows
        const int f   = l % 384;
        const int prg = (bm & 7) * 4 + seg;
        a_src[j] = (bb * 512 + prg * 16) * 1536 + f * 4;
        const int jp = f / 12, f4 = f % 12;
        const int m  = seg * 32 + jp;
        const int c  = f4 >> 1, h = f4 & 1;
        a_dst[j] = (uint32_t)(m * 128 + ((c ^ (m & 7)) << 4) + h * 8);
    }

    // ---- B loader geometry: 768 chunks/iter, thread gets 3 (cp.async) ----
    uint32_t b_dst[3];
    #pragma unroll
    for (int j = 0; j < 3; j++) {
        const int l = tid + 256 * j;
        const int n = l / 6, c = l % 6;
        b_dst[j] = (uint32_t)(32768 + n * 128 + ((c ^ (n & 7)) << 4));
    }

    // ---- per-lane ldmatrix bases ----
    const int rowA = warp_m * 64 + (lane & 15);
    const uint32_t aBase = sbase + (uint32_t)(rowA * 128);
    const int xrA = rowA & 7;
    const int hiA = lane >> 4;
    const int rowB = warp_n * 32 + ((lane >> 4) << 3) + (lane & 7);
    const uint32_t bBase = sbase + 32768u + (uint32_t)(rowB * 128);
    const int xrB = rowB & 7;
    const int hiB = (lane >> 3) & 1;

    float acc[4][4][4];
    #pragma unroll
    for (int i = 0; i < 4; i++)
        #pragma unroll
        for (int j = 0; j < 4; j++)
            #pragma unroll
            for (int k = 0; k < 4; k++) acc[i][j][k] = 0.f;

    // ---- prologue: iter 0 -> buf 0 ----
    {
        const uint8_t* ws = WT + (size_t)(bn * 16) * 768 * 16;
        #pragma unroll
        for (int j = 0; j < 3; j++)
            CP_ASYNC16(sbase + b_dst[j], ws + (tid + 256 * j) * 16);
        CP_COMMIT();
        #pragma unroll
        for (int j = 0; j < 6; j++) {
            float4 v = *(const float4*)(x + a_src[j]);
            uint2 u; u.x = pack2(v.x, v.y); u.y = pack2(v.z, v.w);
            *(uint2*)(smem + a_dst[j]) = u;
        }
        CP_WAIT0();
    }
    __syncthreads();

    int buf = 0;
    for (int it = 0; it < ITERS; it++) {
        float4 va[6];
        const int pf = (it + 1 < ITERS);
        if (pf) {
            const uint8_t* ws = WT + (size_t)(bn * 16 + it + 1) * 768 * 16;
            const uint32_t bd = sbase + (uint32_t)((buf ^ 1) * 16384);
            #pragma unroll
            for (int j = 0; j < 3; j++)
                CP_ASYNC16(bd + b_dst[j], ws + (tid + 256 * j) * 16);
            CP_COMMIT();
            const float* xa = x + (it + 1) * 1536;
            #pragma unroll
            for (int j = 0; j < 6; j++)
                va[j] = *(const float4*)(xa + a_src[j]);
        }

        // ---- compute: 3 ksteps x (6 LDSM.x4 + 16 HMMA) ----
        const uint32_t ab = aBase + (uint32_t)(buf * 16384);
        const uint32_t bbuf = bBase + (uint32_t)(buf * 16384);
        #pragma unroll
        for (int ks = 0; ks < 3; ks++) {
            uint32_t af[4][4], bf[4][2];
            #pragma unroll
            for (int mi = 0; mi < 4; mi++)
                ldsm4(af[mi][0], af[mi][1], af[mi][2], af[mi][3],
                      ab + (uint32_t)(mi * 2048 + (((2 * ks + hiA) ^ xrA) << 4)));
            ldsm4(bf[0][0], bf[0][1], bf[1][0], bf[1][1],
                  bbuf + (uint32_t)(((2 * ks + hiB) ^ xrB) << 4));
            ldsm4(bf[2][0], bf[2][1], bf[3][0], bf[3][1],
                  bbuf + (uint32_t)(2048 + (((2 * ks + hiB) ^ xrB) << 4)));
            #pragma unroll
            for (int mi = 0; mi < 4; mi++)
                #pragma unroll
                for (int ni = 0; ni < 4; ni++)
                    mma_f16(acc[mi][ni], af[mi], bf[ni]);
        }

        if (pf) {
            uint8_t* ad = smem + (buf ^ 1) * 16384;
            #pragma unroll
            for (int j = 0; j < 6; j++) {
                uint2 u; u.x = pack2(va[j].x, va[j].y); u.y = pack2(va[j].z, va[j].w);
                *(uint2*)(ad + a_dst[j]) = u;
            }
            CP_WAIT0();
        }
        __syncthreads();
        buf ^= 1;
    }

    // ---- epilogue: + bias + pos, rows shifted +1 for cls ----
    const int grp = lane >> 2;
    const int tg  = lane & 3;
    const int gn0 = bn * 128 + warp_n * 32;

    float2 bv[4];
    #pragma unroll
    for (int ni = 0; ni < 4; ni++)
        bv[ni] = *(const float2*)(bias + gn0 + ni * 8 + 2 * tg);

    #pragma unroll
    for (int mi = 0; mi < 4; mi++) {
        const int gm0 = bm * 128 + warp_m * 64 + mi * 16 + grp;
        #pragma unroll
        for (int half = 0; half < 2; half++) {
            const int r     = gm0 + half * 8;
            const int bt    = r >> 10;
            const int tok   = r & 1023;
            const int obase = (bt * 1025 + 1 + tok) * 256;
            #pragma unroll
            for (int ni = 0; ni < 4; ni++) {
                const int n = gn0 + ni * 8 + 2 * tg;
                float2 pv = *(const float2*)(pos + obase + n);
                float2 o;
                o.x = acc[mi][ni][half * 2 + 0] + bv[ni].x + pv.x;
                o.y = acc[mi][ni][half * 2 + 1] + bv[ni].y + pv.y;
                *(float2*)(out + obase + n) = o;
            }
        }
    }
}

extern "C" void kernel_launch(void* const* d_in, const int* in_sizes, int n_in,
                              void* d_out, int out_size)
{
    const float* x    = (const float*)d_in[0];
    const float* W    = (const float*)d_in[1];
    const float* bias = (const float*)d_in[2];
    const float* cls  = (const float*)d_in[3];
    const float* pos  = (const float*)d_in[4];
    float* out = (float*)d_out;

    prep_w<<<32, 256>>>(W);

    cudaFuncSetAttribute(patch_gemm, cudaFuncAttributeMaxDynamicSharedMemorySize, 65536);
    dim3 grid(2, 256);
    patch_gemm<<<grid, 256, 65536>>>(x, bias, cls, pos, out);
}

// round 6
// speedup vs baseline: 2.0520x; 1.0365x over previous
#include <cuda_runtime.h>
#include <cuda_fp16.h>
#include <cstdint>

// PatchEmbeddings: out[b,1+n,h] = (patchify(x)[b,n,:] @ W)[h] + bias[h] + pos[b,1+n,h]
//                  out[b,0,h]   = cls[b,0,h] + pos[b,0,h]
// GEMM M=32768, K=768, N=256; m16n8k16 f16, BK=48, warp tile 64x64 (BM=128,BN=256).
// W pre-converted/tiled fp16 (prekernel); B streams via cp.async; A contiguous LDG.

#define ITERS 16

__device__ __align__(16) uint8_t WT[16u * 1536u * 16u];  // 384 KB tiled fp16 W

__device__ __forceinline__ void mma_f16(float* c, const uint32_t* a, const uint32_t* b) {
    asm volatile(
        "mma.sync.aligned.m16n8k16.row.col.f32.f16.f16.f32 "
        "{%0,%1,%2,%3}, {%4,%5,%6,%7}, {%8,%9}, {%0,%1,%2,%3};"
        : "+f"(c[0]), "+f"(c[1]), "+f"(c[2]), "+f"(c[3])
        : "r"(a[0]), "r"(a[1]), "r"(a[2]), "r"(a[3]), "r"(b[0]), "r"(b[1]));
}

__device__ __forceinline__ void ldsm4(uint32_t& r0, uint32_t& r1, uint32_t& r2,
                                      uint32_t& r3, uint32_t addr) {
    asm volatile("ldmatrix.sync.aligned.m8n8.x4.shared.b16 {%0,%1,%2,%3}, [%4];"
                 : "=r"(r0), "=r"(r1), "=r"(r2), "=r"(r3) : "r"(addr));
}

__device__ __forceinline__ uint32_t pack2(float a, float b) {
    __half2 h = __floats2half2_rn(a, b);
    return *reinterpret_cast<uint32_t*>(&h);
}

#define CP_ASYNC16(dst, src) \
    asm volatile("cp.async.cg.shared.global [%0], [%1], 16;" :: "r"(dst), "l"(src) : "memory")
#define CP_COMMIT() asm volatile("cp.async.commit_group;" ::: "memory")
#define CP_WAIT0()  asm volatile("cp.async.wait_group 0;" ::: "memory")

// ---------------- prekernel: W -> fp16, transposed + tile-ordered ----------------
// WT block it holds 1536 chunks; chunk l: n = l/6, c = l%6,
// halves = W[it*48 + c*8 .. +8][n]  (column n of W, 8 consecutive k).
__global__ void prep_w(const float* __restrict__ W) {
    const int it = blockIdx.x;          // 0..15
    const int t  = threadIdx.x;         // 256
    #pragma unroll
    for (int j = 0; j < 6; j++) {
        const int l = t + 256 * j;      // 0..1535
        const int n = l / 6, c = l % 6;
        const float* src = W + (it * 48 + c * 8) * 256 + n;
        uint4 u;
        u.x = pack2(src[0 * 256], src[1 * 256]);
        u.y = pack2(src[2 * 256], src[3 * 256]);
        u.z = pack2(src[4 * 256], src[5 * 256]);
        u.w = pack2(src[6 * 256], src[7 * 256]);
        *(uint4*)(WT + ((size_t)it * 1536 + l) * 16) = u;
    }
}

// ---------------- main kernel ----------------
// smem: A[buf] @ buf*16384 (128 rows x 128B); B[buf] @ 32768 + buf*32768 (256 rows x 128B)
__global__ __launch_bounds__(256, 1)
void patch_gemm(const float* __restrict__ x,
                const float* __restrict__ bias,
                const float* __restrict__ cls,
                const float* __restrict__ pos,
                float* __restrict__ out)
{
    extern __shared__ __align__(128) uint8_t smem[];

    const int tid    = threadIdx.x;
    const int lane   = tid & 31;
    const int warp   = tid >> 5;
    const int warp_m = warp & 1;    // 64 m-rows
    const int warp_n = warp >> 1;   // 64 n-cols
    const int bm     = blockIdx.x;  // 0..255

    const uint32_t sbase = (uint32_t)__cvta_generic_to_shared(smem);

    // ---- fold cls row ----
    if (bm < 32) {
        int o = bm * 1025 * 256 + tid;
        out[o] = cls[bm * 256 + tid] + pos[o];
    }

    // ---- A loader: 1536 float4/iter, 6 per thread ----
    const int bb = bm >> 3;
    int a_src[6];
    uint32_t a_dst[6];
    #pragma unroll
    for (int j = 0; j < 6; j++) {
        const int l   = tid + 256 * j;
        const int seg = l / 384;
        const int f   = l % 384;
        const int prg = (bm & 7) * 4 + seg;
        a_src[j] = (bb * 512 + prg * 16) * 1536 + f * 4;
        const int jp = f / 12, f4 = f % 12;
        const int m  = seg * 32 + jp;
        const int c  = f4 >> 1, h = f4 & 1;
        a_dst[j] = (uint32_t)(m * 128 + ((c ^ (m & 7)) << 4) + h * 8);
    }

    // ---- B loader: 1536 cp.async chunks/iter, 6 per thread ----
    uint32_t b_dst[6];
    #pragma unroll
    for (int j = 0; j < 6; j++) {
        const int l = tid + 256 * j;
        const int n = l / 6, c = l % 6;
        b_dst[j] = (uint32_t)(32768 + n * 128 + ((c ^ (n & 7)) << 4));
    }

    // ---- ldmatrix bases ----
    const int rowA = warp_m * 64 + (lane & 15);
    const uint32_t aBase = sbase + (uint32_t)(rowA * 128);
    const int xrA = rowA & 7;
    const int hiA = lane >> 4;
    const int rowB = warp_n * 64 + ((lane >> 4) << 3) + (lane & 7);
    const uint32_t bBase = sbase + 32768u + (uint32_t)(rowB * 128);
    const int xrB = rowB & 7;           // invariant across nj (stride 16)
    const int hiB = (lane >> 3) & 1;

    float acc[4][8][4];
    #pragma unroll
    for (int i = 0; i < 4; i++)
        #pragma unroll
        for (int j = 0; j < 8; j++)
            #pragma unroll
            for (int k = 0; k < 4; k++) acc[i][j][k] = 0.f;

    // ---- prologue: iter 0 -> buf 0 ----
    {
        const uint8_t* ws = WT;
        #pragma unroll
        for (int j = 0; j < 6; j++)
            CP_ASYNC16(sbase + b_dst[j], ws + (tid + 256 * j) * 16);
        CP_COMMIT();
        #pragma unroll
        for (int j = 0; j < 6; j++) {
            float4 v = *(const float4*)(x + a_src[j]);
            uint2 u; u.x = pack2(v.x, v.y); u.y = pack2(v.z, v.w);
            *(uint2*)(smem + a_dst[j]) = u;
        }
        CP_WAIT0();
    }
    __syncthreads();

    int buf = 0;
    for (int it = 0; it < ITERS; it++) {
        float4 va[6];
        const int pf = (it + 1 < ITERS);
        if (pf) {
            const uint8_t* ws = WT + (size_t)(it + 1) * 1536 * 16;
            const uint32_t bd = sbase + (uint32_t)((buf ^ 1) * 32768);
            #pragma unroll
            for (int j = 0; j < 6; j++)
                CP_ASYNC16(bd + b_dst[j], ws + (tid + 256 * j) * 16);
            CP_COMMIT();
            const float* xa = x + (it + 1) * 1536;
            #pragma unroll
            for (int j = 0; j < 6; j++)
                va[j] = *(const float4*)(xa + a_src[j]);
        }

        // ---- compute: 3 ksteps x (8 LDSM.x4 + 32 HMMA) ----
        const uint32_t ab = aBase + (uint32_t)(buf * 16384);
        const uint32_t bbf = bBase + (uint32_t)(buf * 32768);
        #pragma unroll
        for (int ks = 0; ks < 3; ks++) {
            uint32_t af[4][4], bf[8][2];
            const uint32_t ca = (uint32_t)(((2 * ks + hiA) ^ xrA) << 4);
            const uint32_t cb = (uint32_t)(((2 * ks + hiB) ^ xrB) << 4);
            #pragma unroll
            for (int mi = 0; mi < 4; mi++)
                ldsm4(af[mi][0], af[mi][1], af[mi][2], af[mi][3],
                      ab + (uint32_t)(mi * 2048) + ca);
            #pragma unroll
            for (int nj = 0; nj < 4; nj++)
                ldsm4(bf[2 * nj][0], bf[2 * nj][1], bf[2 * nj + 1][0], bf[2 * nj + 1][1],
                      bbf + (uint32_t)(nj * 2048) + cb);
            #pragma unroll
            for (int mi = 0; mi < 4; mi++)
                #pragma unroll
                for (int ni = 0; ni < 8; ni++)
                    mma_f16(acc[mi][ni], af[mi], bf[ni]);
        }

        if (pf) {
            uint8_t* ad = smem + (buf ^ 1) * 16384;
            #pragma unroll
            for (int j = 0; j < 6; j++) {
                uint2 u; u.x = pack2(va[j].x, va[j].y); u.y = pack2(va[j].z, va[j].w);
                *(uint2*)(ad + a_dst[j]) = u;
            }
            CP_WAIT0();
        }
        __syncthreads();
        buf ^= 1;
    }

    // ---- epilogue: + bias + pos, rows shifted +1 for cls ----
    const int grp = lane >> 2;
    const int tg  = lane & 3;
    const int gn0 = warp_n * 64;

    float2 bv[8];
    #pragma unroll
    for (int ni = 0; ni < 8; ni++)
        bv[ni] = *(const float2*)(bias + gn0 + ni * 8 + 2 * tg);

    #pragma unroll
    for (int mi = 0; mi < 4; mi++) {
        const int gm0 = bm * 128 + warp_m * 64 + mi * 16 + grp;
        #pragma unroll
        for (int half = 0; half < 2; half++) {
            const int r     = gm0 + half * 8;
            const int bt    = r >> 10;
            const int tok   = r & 1023;
            const int obase = (bt * 1025 + 1 + tok) * 256;
            #pragma unroll
            for (int ni = 0; ni < 8; ni++) {
                const int n = gn0 + ni * 8 + 2 * tg;
                float2 pv = *(const float2*)(pos + obase + n);
                float2 o;
                o.x = acc[mi][ni][half * 2 + 0] + bv[ni].x + pv.x;
                o.y = acc[mi][ni][half * 2 + 1] + bv[ni].y + pv.y;
                *(float2*)(out + obase + n) = o;
            }
        }
    }
}

extern "C" void kernel_launch(void* const* d_in, const int* in_sizes, int n_in,
                              void* d_out, int out_size)
{
    const float* x    = (const float*)d_in[0];
    const float* W    = (const float*)d_in[1];
    const float* bias = (const float*)d_in[2];
    const float* cls  = (const float*)d_in[3];
    const float* pos  = (const float*)d_in[4];
    float* out = (float*)d_out;

    prep_w<<<16, 256>>>(W);

    cudaFuncSetAttribute(patch_gemm, cudaFuncAttributeMaxDynamicSharedMemorySize, 98304);
    patch_gemm<<<256, 256, 98304>>>(x, bias, cls, pos, out);
}

// round 7
// speedup vs baseline: 2.2688x; 1.1056x over previous
#include <cuda_runtime.h>
#include <cuda_fp16.h>
#include <cstdint>

// PatchEmbeddings: out[b,1+n,h] = (patchify(x)[b,n,:] @ W)[h] + bias[h] + pos[b,1+n,h]
//                  out[b,0,h]   = cls[b,0,h] + pos[b,0,h]
// GEMM M=32768, K=768, N=256; m16n8k16 f16. BM=128, BN=256, BK=48.
// 512 threads, 16 warps, warp tile 32x64 (spill-free, 4 warps/SMSP).

#define ITERS 16
#define THREADS 512

__device__ __align__(16) uint8_t WT[16u * 1536u * 16u];  // 384 KB tiled fp16 W

__device__ __forceinline__ void mma_f16(float* c, const uint32_t* a, const uint32_t* b) {
    asm volatile(
        "mma.sync.aligned.m16n8k16.row.col.f32.f16.f16.f32 "
        "{%0,%1,%2,%3}, {%4,%5,%6,%7}, {%8,%9}, {%0,%1,%2,%3};"
        : "+f"(c[0]), "+f"(c[1]), "+f"(c[2]), "+f"(c[3])
        : "r"(a[0]), "r"(a[1]), "r"(a[2]), "r"(a[3]), "r"(b[0]), "r"(b[1]));
}

__device__ __forceinline__ void ldsm4(uint32_t& r0, uint32_t& r1, uint32_t& r2,
                                      uint32_t& r3, uint32_t addr) {
    asm volatile("ldmatrix.sync.aligned.m8n8.x4.shared.b16 {%0,%1,%2,%3}, [%4];"
                 : "=r"(r0), "=r"(r1), "=r"(r2), "=r"(r3) : "r"(addr));
}

__device__ __forceinline__ uint32_t pack2(float a, float b) {
    __half2 h = __floats2half2_rn(a, b);
    return *reinterpret_cast<uint32_t*>(&h);
}

#define CP_ASYNC16(dst, src) \
    asm volatile("cp.async.cg.shared.global [%0], [%1], 16;" :: "r"(dst), "l"(src) : "memory")
#define CP_COMMIT() asm volatile("cp.async.commit_group;" ::: "memory")
#define CP_WAIT0()  asm volatile("cp.async.wait_group 0;" ::: "memory")

// ---------------- prekernel: W -> fp16, transposed + tile-ordered ----------------
// chunk l_global = it*1536 + l; l: n = l/6, c = l%6,
// halves = W[it*48 + c*8 .. +8][n].
__global__ void prep_w(const float* __restrict__ W) {
    const int lg = blockIdx.x * 256 + threadIdx.x;   // 0..24575
    const int it = lg / 1536;
    const int l  = lg % 1536;
    const int n  = l / 6, c = l % 6;
    const float* src = W + (it * 48 + c * 8) * 256 + n;
    uint4 u;
    u.x = pack2(src[0 * 256], src[1 * 256]);
    u.y = pack2(src[2 * 256], src[3 * 256]);
    u.z = pack2(src[4 * 256], src[5 * 256]);
    u.w = pack2(src[6 * 256], src[7 * 256]);
    *(uint4*)(WT + (size_t)lg * 16) = u;
}

// ---------------- main kernel ----------------
// smem: A[buf] @ buf*16384 (128 rows x 128B); B[buf] @ 32768 + buf*32768 (256 rows x 128B)
__global__ __launch_bounds__(THREADS, 1)
void patch_gemm(const float* __restrict__ x,
                const float* __restrict__ bias,
                const float* __restrict__ cls,
                const float* __restrict__ pos,
                float* __restrict__ out)
{
    extern __shared__ __align__(128) uint8_t smem[];

    const int tid    = threadIdx.x;
    const int lane   = tid & 31;
    const int warp   = tid >> 5;
    const int warp_m = warp & 3;    // 4 x 32 m-rows
    const int warp_n = warp >> 2;   // 4 x 64 n-cols
    const int bm     = blockIdx.x;  // 0..255

    const uint32_t sbase = (uint32_t)__cvta_generic_to_shared(smem);

    // ---- fold cls row ----
    if (bm < 32 && tid < 256) {
        int o = bm * 1025 * 256 + tid;
        out[o] = cls[bm * 256 + tid] + pos[o];
    }

    // ---- A loader: 1536 float4/iter, 3 per thread ----
    const int bb = bm >> 3;
    int a_src[3];
    uint32_t a_dst[3];
    #pragma unroll
    for (int j = 0; j < 3; j++) {
        const int l   = tid + THREADS * j;
        const int seg = l / 384;
        const int f   = l % 384;
        const int prg = (bm & 7) * 4 + seg;
        a_src[j] = (bb * 512 + prg * 16) * 1536 + f * 4;
        const int jp = f / 12, f4 = f % 12;
        const int m  = seg * 32 + jp;
        const int c  = f4 >> 1, h = f4 & 1;
        a_dst[j] = (uint32_t)(m * 128 + ((c ^ (m & 7)) << 4) + h * 8);
    }

    // ---- B loader: 1536 cp.async chunks/iter, 3 per thread ----
    uint32_t b_dst[3];
    #pragma unroll
    for (int j = 0; j < 3; j++) {
        const int l = tid + THREADS * j;
        const int n = l / 6, c = l % 6;
        b_dst[j] = (uint32_t)(32768 + n * 128 + ((c ^ (n & 7)) << 4));
    }

    // ---- ldmatrix bases ----
    const int rowA = warp_m * 32 + (lane & 15);
    const uint32_t aBase = sbase + (uint32_t)(rowA * 128);
    const int xrA = rowA & 7;
    const int hiA = lane >> 4;
    const int rowB = warp_n * 64 + ((lane >> 4) << 3) + (lane & 7);
    const uint32_t bBase = sbase + 32768u + (uint32_t)(rowB * 128);
    const int xrB = rowB & 7;           // invariant across nj (stride 16)
    const int hiB = (lane >> 3) & 1;

    float acc[2][8][4];
    #pragma unroll
    for (int i = 0; i < 2; i++)
        #pragma unroll
        for (int j = 0; j < 8; j++)
            #pragma unroll
            for (int k = 0; k < 4; k++) acc[i][j][k] = 0.f;

    // ---- prologue: iter 0 -> buf 0 ----
    {
        #pragma unroll
        for (int j = 0; j < 3; j++)
            CP_ASYNC16(sbase + b_dst[j], WT + (tid + THREADS * j) * 16);
        CP_COMMIT();
        #pragma unroll
        for (int j = 0; j < 3; j++) {
            float4 v = *(const float4*)(x + a_src[j]);
            uint2 u; u.x = pack2(v.x, v.y); u.y = pack2(v.z, v.w);
            *(uint2*)(smem + a_dst[j]) = u;
        }
        CP_WAIT0();
    }
    __syncthreads();

    int buf = 0;
    for (int it = 0; it < ITERS; it++) {
        float4 va[3];
        const int pf = (it + 1 < ITERS);
        if (pf) {
            const uint8_t* ws = WT + (size_t)(it + 1) * 1536 * 16;
            const uint32_t bd = sbase + (uint32_t)((buf ^ 1) * 32768);
            #pragma unroll
            for (int j = 0; j < 3; j++)
                CP_ASYNC16(bd + b_dst[j], ws + (tid + THREADS * j) * 16);
            CP_COMMIT();
            const float* xa = x + (it + 1) * 1536;
            #pragma unroll
            for (int j = 0; j < 3; j++)
                va[j] = *(const float4*)(xa + a_src[j]);
        }

        // ---- compute: 3 ksteps x (6 LDSM.x4 + 16 HMMA) ----
        const uint32_t ab  = aBase + (uint32_t)(buf * 16384);
        const uint32_t bbf = bBase + (uint32_t)(buf * 32768);
        #pragma unroll
        for (int ks = 0; ks < 3; ks++) {
            uint32_t af[2][4], bf[8][2];
            const uint32_t ca = (uint32_t)(((2 * ks + hiA) ^ xrA) << 4);
            const uint32_t cb = (uint32_t)(((2 * ks + hiB) ^ xrB) << 4);
            #pragma unroll
            for (int mi = 0; mi < 2; mi++)
                ldsm4(af[mi][0], af[mi][1], af[mi][2], af[mi][3],
                      ab + (uint32_t)(mi * 2048) + ca);
            #pragma unroll
            for (int nj = 0; nj < 4; nj++)
                ldsm4(bf[2 * nj][0], bf[2 * nj][1], bf[2 * nj + 1][0], bf[2 * nj + 1][1],
                      bbf + (uint32_t)(nj * 2048) + cb);
            #pragma unroll
            for (int mi = 0; mi < 2; mi++)
                #pragma unroll
                for (int ni = 0; ni < 8; ni++)
                    mma_f16(acc[mi][ni], af[mi], bf[ni]);
        }

        if (pf) {
            uint8_t* ad = smem + (buf ^ 1) * 16384;
            #pragma unroll
            for (int j = 0; j < 3; j++) {
                uint2 u; u.x = pack2(va[j].x, va[j].y); u.y = pack2(va[j].z, va[j].w);
                *(uint2*)(ad + a_dst[j]) = u;
            }
            CP_WAIT0();
        }
        __syncthreads();
        buf ^= 1;
    }

    // ---- epilogue: + bias + pos, rows shifted +1 for cls ----
    const int grp = lane >> 2;
    const int tg  = lane & 3;
    const int gn0 = warp_n * 64;

    float2 bv[8];
    #pragma unroll
    for (int ni = 0; ni < 8; ni++)
        bv[ni] = *(const float2*)(bias + gn0 + ni * 8 + 2 * tg);

    #pragma unroll
    for (int mi = 0; mi < 2; mi++) {
        const int gm0 = bm * 128 + warp_m * 32 + mi * 16 + grp;
        #pragma unroll
        for (int half = 0; half < 2; half++) {
            const int r     = gm0 + half * 8;
            const int bt    = r >> 10;
            const int tok   = r & 1023;
            const int obase = (bt * 1025 + 1 + tok) * 256;
            #pragma unroll
            for (int ni = 0; ni < 8; ni++) {
                const int n = gn0 + ni * 8 + 2 * tg;
                float2 pv = *(const float2*)(pos + obase + n);
                float2 o;
                o.x = acc[mi][ni][half * 2 + 0] + bv[ni].x + pv.x;
                o.y = acc[mi][ni][half * 2 + 1] + bv[ni].y + pv.y;
                *(float2*)(out + obase + n) = o;
            }
        }
    }
}

extern "C" void kernel_launch(void* const* d_in, const int* in_sizes, int n_in,
                              void* d_out, int out_size)
{
    const float* x    = (const float*)d_in[0];
    const float* W    = (const float*)d_in[1];
    const float* bias = (const float*)d_in[2];
    const float* cls  = (const float*)d_in[3];
    const float* pos  = (const float*)d_in[4];
    float* out = (float*)d_out;

    prep_w<<<96, 256>>>(W);

    cudaFuncSetAttribute(patch_gemm, cudaFuncAttributeMaxDynamicSharedMemorySize, 98304);
    patch_gemm<<<256, THREADS, 98304>>>(x, bias, cls, pos, out);
}